// round 1
// baseline (speedup 1.0000x reference)
#include <cuda_runtime.h>
#include <cstdint>

// ---------------------------------------------------------------------------
// GraphFusionLayer: proj(a/t)+LN+relu -> GAT1(relu) -> GAT2 -> mean -> fc+LN
// Key structural insight: only nodes 0 and 1 have non-self edges, so both GAT
// layers are plain GEMM+bias(+relu) for all rows except a 2-row fixup.
// Round 1: fp32 SIMT SGEMM chain (correctness + perf baseline).
// ---------------------------------------------------------------------------

namespace {
constexpr int BB  = 16384;       // batch
constexpr int DD  = 1024;        // hidden
constexpr int N2  = 2 * BB;      // 32768 graph nodes
constexpr int HD  = 2 * DD;      // 2048 (gat1 out, heads*D)
constexpr float LN_EPS = 1e-5f;
constexpr float SLOPE  = 0.2f;
}

// Scratch (device globals: allocation-free per harness rules)
__device__ float g_bufA[(size_t)BB * DD];     // proj-audio pre-LN; reused for fc pre-LN
__device__ float g_bufT[(size_t)BB * DD];     // proj-text pre-LN
__device__ float g_nodes[(size_t)N2 * DD];    // interleaved LN+relu outputs
__device__ float g_g1[(size_t)N2 * HD];       // gat1 output (post bias+relu)
__device__ float g_g2[(size_t)N2 * DD];       // gat2 output (post bias)
__device__ float g_fused[(size_t)BB * DD];    // pair mean
__device__ float g_raw1[2 * HD];              // raw xp rows 0,1 (gat1, pre-bias)
__device__ float g_raw2[2 * DD];              // raw xq rows 0,1 (gat2, pre-bias)

// ---------------- SGEMM: C[M,N] = A[M,K] * W[N,K]^T (+bias) (+relu) --------
// 128x128 block tile, BK=16, 256 threads, 8x8 per thread.
template<bool BIAS, bool RELU>
__global__ __launch_bounds__(256, 2)
void sgemm_kernel(const float* __restrict__ A, const float* __restrict__ W,
                  const float* __restrict__ bias, float* __restrict__ C,
                  int M, int N, int K, float* __restrict__ raw2rows)
{
    constexpr int BM = 128, BN = 128, BK = 16;
    __shared__ float As[BK][BM + 4];
    __shared__ float Bs[BK][BN + 4];

    const int t  = threadIdx.x;
    const int bm = blockIdx.y * BM;
    const int bn = blockIdx.x * BN;
    const int tm = t >> 4;            // 0..15
    const int tn = t & 15;            // 0..15

    const int lrow = t >> 2;          // 0..63
    const int lcol = (t & 3) * 4;     // 0,4,8,12

    const float* Ap = A + (size_t)(bm + lrow) * K + lcol;
    const float* Wp = W + (size_t)(bn + lrow) * K + lcol;

    float acc[8][8];
    #pragma unroll
    for (int i = 0; i < 8; i++)
        #pragma unroll
        for (int j = 0; j < 8; j++) acc[i][j] = 0.f;

    for (int k0 = 0; k0 < K; k0 += BK) {
        const float4 a0 = *(const float4*)(Ap + k0);
        const float4 a1 = *(const float4*)(Ap + (size_t)64 * K + k0);
        const float4 w0 = *(const float4*)(Wp + k0);
        const float4 w1 = *(const float4*)(Wp + (size_t)64 * K + k0);
        __syncthreads();
        As[lcol+0][lrow]    = a0.x; As[lcol+1][lrow]    = a0.y;
        As[lcol+2][lrow]    = a0.z; As[lcol+3][lrow]    = a0.w;
        As[lcol+0][lrow+64] = a1.x; As[lcol+1][lrow+64] = a1.y;
        As[lcol+2][lrow+64] = a1.z; As[lcol+3][lrow+64] = a1.w;
        Bs[lcol+0][lrow]    = w0.x; Bs[lcol+1][lrow]    = w0.y;
        Bs[lcol+2][lrow]    = w0.z; Bs[lcol+3][lrow]    = w0.w;
        Bs[lcol+0][lrow+64] = w1.x; Bs[lcol+1][lrow+64] = w1.y;
        Bs[lcol+2][lrow+64] = w1.z; Bs[lcol+3][lrow+64] = w1.w;
        __syncthreads();
        #pragma unroll
        for (int kk = 0; kk < BK; kk++) {
            const float4 av0 = *(const float4*)&As[kk][tm * 8];
            const float4 av1 = *(const float4*)&As[kk][tm * 8 + 4];
            const float4 bv0 = *(const float4*)&Bs[kk][tn * 8];
            const float4 bv1 = *(const float4*)&Bs[kk][tn * 8 + 4];
            const float a[8] = {av0.x, av0.y, av0.z, av0.w, av1.x, av1.y, av1.z, av1.w};
            const float b[8] = {bv0.x, bv0.y, bv0.z, bv0.w, bv1.x, bv1.y, bv1.z, bv1.w};
            #pragma unroll
            for (int i = 0; i < 8; i++)
                #pragma unroll
                for (int j = 0; j < 8; j++)
                    acc[i][j] = fmaf(a[i], b[j], acc[i][j]);
        }
    }

    float bv[8];
    if (BIAS) {
        #pragma unroll
        for (int j = 0; j < 8; j++) bv[j] = bias[bn + tn * 8 + j];
    }
    #pragma unroll
    for (int i = 0; i < 8; i++) {
        const int row = bm + tm * 8 + i;
        float* crow = C + (size_t)row * N + bn + tn * 8;
        if (raw2rows != nullptr && row < 2) {     // capture pre-bias xp for GAT fixup
            #pragma unroll
            for (int j = 0; j < 8; j++)
                raw2rows[row * N + bn + tn * 8 + j] = acc[i][j];
        }
        float tmp[8];
        #pragma unroll
        for (int j = 0; j < 8; j++) {
            float v = acc[i][j];
            if (BIAS) v += bv[j];
            if (RELU) v = fmaxf(v, 0.f);
            tmp[j] = v;
        }
        *(float4*)(crow)     = make_float4(tmp[0], tmp[1], tmp[2], tmp[3]);
        *(float4*)(crow + 4) = make_float4(tmp[4], tmp[5], tmp[6], tmp[7]);
    }
}

// ---------------- LayerNorm over D=1024 per row (+optional relu) -----------
// 256 threads, one float4 per thread. out row = r*out_mul + out_off (interleave).
template<bool RELU>
__global__ __launch_bounds__(256)
void ln_kernel(const float* __restrict__ in, float* __restrict__ out,
               const float* __restrict__ gamma, const float* __restrict__ beta,
               int out_mul, int out_off)
{
    const int r   = blockIdx.x;
    const int tid = threadIdx.x;
    const float4 xv = ((const float4*)(in + (size_t)r * DD))[tid];
    float s = xv.x + xv.y + xv.z + xv.w;
    float q = xv.x * xv.x + xv.y * xv.y + xv.z * xv.z + xv.w * xv.w;
    #pragma unroll
    for (int o = 16; o > 0; o >>= 1) {
        s += __shfl_xor_sync(0xffffffffu, s, o);
        q += __shfl_xor_sync(0xffffffffu, q, o);
    }
    __shared__ float sh_s[8], sh_q[8];
    const int lane = tid & 31, wid = tid >> 5;
    if (lane == 0) { sh_s[wid] = s; sh_q[wid] = q; }
    __syncthreads();
    if (wid == 0) {
        s = (lane < 8) ? sh_s[lane] : 0.f;
        q = (lane < 8) ? sh_q[lane] : 0.f;
        #pragma unroll
        for (int o = 4; o > 0; o >>= 1) {
            s += __shfl_xor_sync(0xffffffffu, s, o);
            q += __shfl_xor_sync(0xffffffffu, q, o);
        }
        if (lane == 0) { sh_s[0] = s; sh_q[0] = q; }
    }
    __syncthreads();
    const float mu  = sh_s[0] * (1.f / DD);
    const float var = sh_q[0] * (1.f / DD) - mu * mu;
    const float inv = rsqrtf(var + LN_EPS);
    const float4 g = ((const float4*)gamma)[tid];
    const float4 b = ((const float4*)beta)[tid];
    float4 y;
    y.x = (xv.x - mu) * inv * g.x + b.x;
    y.y = (xv.y - mu) * inv * g.y + b.y;
    y.z = (xv.z - mu) * inv * g.z + b.z;
    y.w = (xv.w - mu) * inv * g.w + b.w;
    if (RELU) {
        y.x = fmaxf(y.x, 0.f); y.y = fmaxf(y.y, 0.f);
        y.z = fmaxf(y.z, 0.f); y.w = fmaxf(y.w, 0.f);
    }
    ((float4*)(out + (size_t)(r * out_mul + out_off) * DD))[tid] = y;
}

// ---------------- GAT 2-row attention fixup --------------------------------
// raw: [2][H*C] pre-bias xp for nodes 0,1. Recompute rows 0,1 of `out`:
//   out0 = softmax([lrelu(s0+d0), lrelu(s1+d0)]) . [xp0, xp1]
//   out1 = softmax([lrelu(s1+d1), lrelu(s0+d1)]) . [xp1, xp0]
// then +bias (+relu).
template<int H, bool RELU>
__global__ __launch_bounds__(256)
void gat_fixup(const float* __restrict__ raw, const float* __restrict__ a_src,
               const float* __restrict__ a_dst, const float* __restrict__ bias,
               float* __restrict__ out)
{
    constexpr int C  = DD;
    constexpr int RL = H * C;
    const int tid = threadIdx.x;

    float p[4 * H];
    #pragma unroll
    for (int q = 0; q < 4 * H; q++) p[q] = 0.f;
    for (int c = tid; c < C; c += 256) {
        #pragma unroll
        for (int h = 0; h < H; h++) {
            const float x0 = raw[h * C + c];
            const float x1 = raw[RL + h * C + c];
            const float vs = a_src[h * C + c];
            const float vd = a_dst[h * C + c];
            p[h * 4 + 0] += x0 * vs;   // s0
            p[h * 4 + 1] += x0 * vd;   // d0
            p[h * 4 + 2] += x1 * vs;   // s1
            p[h * 4 + 3] += x1 * vd;   // d1
        }
    }
    __shared__ float red[4 * H][256];
    #pragma unroll
    for (int q = 0; q < 4 * H; q++) red[q][tid] = p[q];
    __syncthreads();
    for (int s = 128; s > 0; s >>= 1) {
        if (tid < s) {
            #pragma unroll
            for (int q = 0; q < 4 * H; q++) red[q][tid] += red[q][tid + s];
        }
        __syncthreads();
    }
    __shared__ float wts[H][4];   // [h] = {w(x0->o0), w(x1->o0), w(x1->o1), w(x0->o1)}
    if (tid == 0) {
        for (int h = 0; h < H; h++) {
            const float s0 = red[h * 4 + 0][0];
            const float d0 = red[h * 4 + 1][0];
            const float s1 = red[h * 4 + 2][0];
            const float d1 = red[h * 4 + 3][0];
            const float e00 = (s0 + d0 > 0.f) ? (s0 + d0) : SLOPE * (s0 + d0);
            const float e10 = (s1 + d0 > 0.f) ? (s1 + d0) : SLOPE * (s1 + d0);
            const float m0 = fmaxf(e00, e10);
            const float a0 = expf(e00 - m0), c0 = expf(e10 - m0);
            const float r0 = 1.f / (a0 + c0);
            wts[h][0] = a0 * r0;
            wts[h][1] = c0 * r0;
            const float e11 = (s1 + d1 > 0.f) ? (s1 + d1) : SLOPE * (s1 + d1);
            const float e01 = (s0 + d1 > 0.f) ? (s0 + d1) : SLOPE * (s0 + d1);
            const float m1 = fmaxf(e11, e01);
            const float a1 = expf(e11 - m1), c1 = expf(e01 - m1);
            const float r1 = 1.f / (a1 + c1);
            wts[h][2] = a1 * r1;
            wts[h][3] = c1 * r1;
        }
    }
    __syncthreads();
    for (int idx = tid; idx < RL; idx += 256) {
        const int h = idx / C;
        const float x0 = raw[idx];
        const float x1 = raw[RL + idx];
        const float bb = bias[idx];
        float o0 = wts[h][0] * x0 + wts[h][1] * x1 + bb;
        float o1 = wts[h][2] * x1 + wts[h][3] * x0 + bb;
        if (RELU) { o0 = fmaxf(o0, 0.f); o1 = fmaxf(o1, 0.f); }
        out[idx]      = o0;
        out[RL + idx] = o1;
    }
}

// ---------------- pair mean: fused[b] = (g2[2b]+g2[2b+1])/2 ----------------
__global__ __launch_bounds__(256)
void mean_pairs(const float* __restrict__ g2, float* __restrict__ fused)
{
    const int f = blockIdx.x * blockDim.x + threadIdx.x;   // over B*D/4
    constexpr int RL4 = DD / 4;
    if (f < BB * RL4) {
        const int b = f / RL4;
        const int r = f - b * RL4;
        const float4 u = ((const float4*)g2)[(size_t)(2 * b) * RL4 + r];
        const float4 v = ((const float4*)g2)[(size_t)(2 * b + 1) * RL4 + r];
        float4 y;
        y.x = 0.5f * (u.x + v.x);
        y.y = 0.5f * (u.y + v.y);
        y.z = 0.5f * (u.z + v.z);
        y.w = 0.5f * (u.w + v.w);
        ((float4*)fused)[f] = y;
    }
}

// ---------------------------------------------------------------------------
extern "C" void kernel_launch(void* const* d_in, const int* in_sizes, int n_in,
                              void* d_out, int out_size)
{
    const float* audio = (const float*)d_in[0];
    const float* text  = (const float*)d_in[1];
    const float* Wa    = (const float*)d_in[2];
    const float* ba    = (const float*)d_in[3];
    const float* lna_g = (const float*)d_in[4];
    const float* lna_b = (const float*)d_in[5];
    const float* Wt    = (const float*)d_in[6];
    const float* bt    = (const float*)d_in[7];
    const float* lnt_g = (const float*)d_in[8];
    const float* lnt_b = (const float*)d_in[9];
    const float* W1    = (const float*)d_in[10];
    const float* as1   = (const float*)d_in[11];
    const float* ad1   = (const float*)d_in[12];
    const float* b1    = (const float*)d_in[13];
    const float* W2    = (const float*)d_in[14];
    const float* as2   = (const float*)d_in[15];
    const float* ad2   = (const float*)d_in[16];
    const float* b2    = (const float*)d_in[17];
    const float* Wf    = (const float*)d_in[18];
    const float* bf    = (const float*)d_in[19];
    const float* lnf_g = (const float*)d_in[20];
    const float* lnf_b = (const float*)d_in[21];
    float* out = (float*)d_out;

    float *bufA, *bufT, *nodes, *g1, *g2, *fused, *raw1, *raw2;
    cudaGetSymbolAddress((void**)&bufA,  g_bufA);
    cudaGetSymbolAddress((void**)&bufT,  g_bufT);
    cudaGetSymbolAddress((void**)&nodes, g_nodes);
    cudaGetSymbolAddress((void**)&g1,    g_g1);
    cudaGetSymbolAddress((void**)&g2,    g_g2);
    cudaGetSymbolAddress((void**)&fused, g_fused);
    cudaGetSymbolAddress((void**)&raw1,  g_raw1);
    cudaGetSymbolAddress((void**)&raw2,  g_raw2);

    const dim3 blk(256);

    // Stage A: projections + LN + relu, interleaved into node buffer
    const dim3 gproj(DD / 128, BB / 128);
    sgemm_kernel<true, false><<<gproj, blk>>>(audio, Wa, ba, bufA, BB, DD, DD, nullptr);
    sgemm_kernel<true, false><<<gproj, blk>>>(text,  Wt, bt, bufT, BB, DD, DD, nullptr);
    ln_kernel<true><<<BB, blk>>>(bufA, nodes, lna_g, lna_b, 2, 0);
    ln_kernel<true><<<BB, blk>>>(bufT, nodes, lnt_g, lnt_b, 2, 1);

    // Stage B: gat1 = GEMM + bias + relu, then 2-row attention fixup
    const dim3 ggat1(HD / 128, N2 / 128);
    sgemm_kernel<true, true><<<ggat1, blk>>>(nodes, W1, b1, g1, N2, HD, DD, raw1);
    gat_fixup<2, true><<<1, blk>>>(raw1, as1, ad1, b1, g1);

    // Stage C: gat2 = GEMM + bias, then fixup
    const dim3 ggat2(DD / 128, N2 / 128);
    sgemm_kernel<true, false><<<ggat2, blk>>>(g1, W2, b2, g2, N2, DD, HD, raw2);
    gat_fixup<1, false><<<1, blk>>>(raw2, as2, ad2, b2, g2);

    // Stage D: pair mean, fc GEMM + bias, final LN
    mean_pairs<<<(BB * DD / 4 + 255) / 256, blk>>>(g2, fused);
    sgemm_kernel<true, false><<<gproj, blk>>>(fused, Wf, bf, bufA, BB, DD, DD, nullptr);
    ln_kernel<false><<<BB, blk>>>(bufA, out, lnf_g, lnf_b, 1, 0);
}

// round 5
// speedup vs baseline: 1.9376x; 1.9376x over previous
#include <cuda_runtime.h>
#include <cuda_fp16.h>
#include <cstdint>

// ---------------------------------------------------------------------------
// GraphFusionLayer via mma.sync (sm_100 baseline PTX — tcgen05 is NOT
// available under the harness's compile target). All 4 GEMM stages run as
// fp16 hi/lo (3-term) tensor-core GEMMs with fp32 accumulators.
// GAT layers = GEMM + 2-row attention fixup (only nodes 0,1 have real edges).
// ---------------------------------------------------------------------------

namespace {
constexpr int BB = 16384, DD = 1024, N2 = 2 * BB, HD = 2 * DD;
constexpr float LN_EPS = 1e-5f, SLOPE = 0.2f;

constexpr int BM = 128, BN = 128, BK = 32;     // tile dims (fp16 elems)
constexpr int PITCHB = 80;                      // 32 fp16 padded to 40 -> 80 bytes
constexpr int ASZ = BM * PITCHB;                // 10240 B per matrix buffer
constexpr int OFF_AH = 0;
constexpr int OFF_AL = ASZ;
constexpr int OFF_BH = 2 * ASZ;
constexpr int OFF_BL = 3 * ASZ;
constexpr int STAGE = 4 * ASZ;                  // 40960 B
constexpr int NSTAGE = 3;
constexpr int SMEM_GEMM = NSTAGE * STAGE;       // 122880 B
}

// ---------------- device scratch (allocation-free) -------------------------
__device__ __align__(256) __half g_ah[(size_t)BB * DD], g_al[(size_t)BB * DD];
__device__ __align__(256) __half g_th[(size_t)BB * DD], g_tl[(size_t)BB * DD];
__device__ __align__(256) __half g_Wah[DD * DD], g_Wal[DD * DD];
__device__ __align__(256) __half g_Wth[DD * DD], g_Wtl[DD * DD];
__device__ __align__(256) __half g_W1h[HD * DD], g_W1l[HD * DD];
__device__ __align__(256) __half g_W2h[DD * HD], g_W2l[DD * HD];
__device__ __align__(256) __half g_Wfh[DD * DD], g_Wfl[DD * DD];
__device__ __align__(256) float g_proj0[(size_t)BB * DD];   // pre-LN; reused for fc
__device__ __align__(256) float g_proj1[(size_t)BB * DD];
__device__ __align__(256) __half g_nh[(size_t)N2 * DD], g_nl[(size_t)N2 * DD];
__device__ __align__(256) __half g_g1h[(size_t)N2 * HD], g_g1l[(size_t)N2 * HD];
__device__ __align__(256) float g_g2[(size_t)N2 * DD];
__device__ __align__(256) __half g_fh[(size_t)BB * DD], g_fl[(size_t)BB * DD];
__device__ __align__(256) float g_raw1[2 * HD];
__device__ __align__(256) float g_raw2[2 * DD];

// ---------------- PTX helpers ----------------------------------------------
__device__ __forceinline__ uint32_t smem_u32(const void* p) {
    uint32_t a;
    asm("{ .reg .u64 t; cvta.to.shared.u64 t, %1; cvt.u32.u64 %0, t; }" : "=r"(a) : "l"(p));
    return a;
}
__device__ __forceinline__ void cp16(uint32_t dst, const void* src) {
    asm volatile("cp.async.cg.shared.global [%0], [%1], 16;" :: "r"(dst), "l"(src));
}
__device__ __forceinline__ void cp_commit() { asm volatile("cp.async.commit_group;" ::: "memory"); }
template<int N> __device__ __forceinline__ void cp_wait() {
    asm volatile("cp.async.wait_group %0;" :: "n"(N) : "memory");
}
__device__ __forceinline__ void ldm_x4(uint32_t* r, uint32_t addr) {
    asm volatile("ldmatrix.sync.aligned.m8n8.x4.shared.b16 {%0,%1,%2,%3}, [%4];"
                 : "=r"(r[0]), "=r"(r[1]), "=r"(r[2]), "=r"(r[3]) : "r"(addr));
}
__device__ __forceinline__ void mma16816(float* c, const uint32_t* a,
                                         uint32_t b0, uint32_t b1) {
    asm volatile(
        "mma.sync.aligned.m16n8k16.row.col.f32.f16.f16.f32 "
        "{%0,%1,%2,%3}, {%4,%5,%6,%7}, {%8,%9}, {%0,%1,%2,%3};"
        : "+f"(c[0]), "+f"(c[1]), "+f"(c[2]), "+f"(c[3])
        : "r"(a[0]), "r"(a[1]), "r"(a[2]), "r"(a[3]), "r"(b0), "r"(b1));
}

// ---------------- stage loader ---------------------------------------------
__device__ __forceinline__ void load_stage(
    uint32_t st, const __half* __restrict__ Ah, const __half* __restrict__ Al,
    const __half* __restrict__ Bh, const __half* __restrict__ Bl,
    int bm, int bn, int K, int k0, int t)
{
    #pragma unroll
    for (int i = t; i < 512; i += 256) {         // 128 rows x 4 16B-chunks
        const int r = i >> 2, c = i & 3;
        const uint32_t d = (uint32_t)(r * PITCHB + c * 16);
        const size_t ga = (size_t)(bm + r) * K + k0 + c * 8;
        const size_t gb = (size_t)(bn + r) * K + k0 + c * 8;
        cp16(st + OFF_AH + d, Ah + ga);
        cp16(st + OFF_AL + d, Al + ga);
        cp16(st + OFF_BH + d, Bh + gb);
        cp16(st + OFF_BL + d, Bl + gb);
    }
    cp_commit();
}

// ---------------- mma.sync GEMM: C = A * W^T (+bias) -----------------------
// MODE 0: write fp32 (acc+bias).  MODE 1: write hi/lo fp16 of relu(acc+bias).
template<int MODE>
__global__ __launch_bounds__(256)
void gemm_tc(const __half* __restrict__ Ah, const __half* __restrict__ Al,
             const __half* __restrict__ Bh, const __half* __restrict__ Bl,
             const float* __restrict__ bias,
             float* __restrict__ Cf,
             __half* __restrict__ Ch, __half* __restrict__ Cl,
             int M, int N, int K, float* __restrict__ raw2)
{
    extern __shared__ char smem[];
    const uint32_t sb = smem_u32(smem);

    const int t    = threadIdx.x;
    const int lane = t & 31;
    const int wid  = t >> 5;
    const int wm   = wid & 3;        // warp row   (4) -> 32 rows each
    const int wn   = wid >> 2;       // warp col   (2) -> 64 cols each
    const int bm   = blockIdx.y * BM;
    const int bn   = blockIdx.x * BN;
    const int C    = K / BK;

    float acc[2][8][4];
    #pragma unroll
    for (int mt = 0; mt < 2; ++mt)
        #pragma unroll
        for (int nt = 0; nt < 8; ++nt)
            #pragma unroll
            for (int q = 0; q < 4; ++q) acc[mt][nt][q] = 0.f;

    // prologue: prime stages 0 and 1
    load_stage(sb,         Ah, Al, Bh, Bl, bm, bn, K, 0,  t);
    load_stage(sb + STAGE, Ah, Al, Bh, Bl, bm, bn, K, BK, t);

    for (int c = 0; c < C; ++c) {
        if (c + 1 < C) cp_wait<1>(); else cp_wait<0>();
        __syncthreads();                          // stage-c ready; buf reuse safe
        if (c + 2 < C)
            load_stage(sb + ((c + 2) % NSTAGE) * STAGE, Ah, Al, Bh, Bl,
                       bm, bn, K, (c + 2) * BK, t);

        const uint32_t stg = sb + (c % NSTAGE) * STAGE;
        #pragma unroll
        for (int ks = 0; ks < 2; ++ks) {
            const uint32_t colb = (uint32_t)((ks * 16 + (lane >> 4) * 8) * 2);
            uint32_t ah[2][4], al_[2][4], bh[4][4], bl[4][4];
            #pragma unroll
            for (int mt = 0; mt < 2; ++mt) {
                const uint32_t addr = stg + OFF_AH +
                    (uint32_t)((wm * 32 + mt * 16 + (lane & 15)) * PITCHB) + colb;
                ldm_x4(ah[mt],  addr);
                ldm_x4(al_[mt], addr + (OFF_AL - OFF_AH));
            }
            #pragma unroll
            for (int nb = 0; nb < 4; ++nb) {
                const uint32_t addr = stg + OFF_BH +
                    (uint32_t)((wn * 64 + nb * 16 + (lane & 15)) * PITCHB) + colb;
                ldm_x4(bh[nb], addr);
                ldm_x4(bl[nb], addr + (OFF_BL - OFF_BH));
            }
            #pragma unroll
            for (int mt = 0; mt < 2; ++mt)
                #pragma unroll
                for (int nt = 0; nt < 8; ++nt) {
                    const int nb = nt >> 1, o = nt & 1;
                    float* cc = acc[mt][nt];
                    mma16816(cc, ah[mt],  bh[nb][o], bh[nb][2 + o]);  // Ah*Bh
                    mma16816(cc, al_[mt], bh[nb][o], bh[nb][2 + o]);  // Al*Bh
                    mma16816(cc, ah[mt],  bl[nb][o], bl[nb][2 + o]);  // Ah*Bl
                }
        }
    }

    // epilogue (registers only; no smem dependence)
    const int r0 = lane >> 2;
    const int cp = (lane & 3) * 2;
    #pragma unroll
    for (int mt = 0; mt < 2; ++mt) {
        #pragma unroll
        for (int nt = 0; nt < 8; ++nt) {
            const int gr0 = bm + wm * 32 + mt * 16 + r0;
            const int gr1 = gr0 + 8;
            const int gc  = bn + wn * 64 + nt * 8 + cp;
            float v00 = acc[mt][nt][0], v01 = acc[mt][nt][1];
            float v10 = acc[mt][nt][2], v11 = acc[mt][nt][3];
            if (raw2 != nullptr && gr0 < 2) {        // pre-bias capture (rows 0,1)
                raw2[(size_t)gr0 * N + gc]     = v00;
                raw2[(size_t)gr0 * N + gc + 1] = v01;
            }
            const float b0 = bias[gc], b1 = bias[gc + 1];
            v00 += b0; v01 += b1; v10 += b0; v11 += b1;
            if (MODE == 0) {
                *(float2*)(Cf + (size_t)gr0 * N + gc) = make_float2(v00, v01);
                *(float2*)(Cf + (size_t)gr1 * N + gc) = make_float2(v10, v11);
            } else {
                v00 = fmaxf(v00, 0.f); v01 = fmaxf(v01, 0.f);
                v10 = fmaxf(v10, 0.f); v11 = fmaxf(v11, 0.f);
                const __half h00 = __float2half_rn(v00), h01 = __float2half_rn(v01);
                const __half h10 = __float2half_rn(v10), h11 = __float2half_rn(v11);
                *(__half2*)(Ch + (size_t)gr0 * N + gc) = __halves2half2(h00, h01);
                *(__half2*)(Ch + (size_t)gr1 * N + gc) = __halves2half2(h10, h11);
                *(__half2*)(Cl + (size_t)gr0 * N + gc) = __halves2half2(
                    __float2half_rn(v00 - __half2float(h00)),
                    __float2half_rn(v01 - __half2float(h01)));
                *(__half2*)(Cl + (size_t)gr1 * N + gc) = __halves2half2(
                    __float2half_rn(v10 - __half2float(h10)),
                    __float2half_rn(v11 - __half2float(h11)));
            }
        }
    }
}

// ---------------- fp32 -> fp16 hi/lo conversion ----------------------------
__global__ __launch_bounds__(256)
void cvt_hilo(const float4* __restrict__ x, __half2* __restrict__ h,
              __half2* __restrict__ l, int n4)
{
    const int i = blockIdx.x * blockDim.x + threadIdx.x;
    if (i < n4) {
        const float4 v = x[i];
        const __half h0 = __float2half_rn(v.x), h1 = __float2half_rn(v.y);
        const __half h2 = __float2half_rn(v.z), h3 = __float2half_rn(v.w);
        h[2 * i + 0] = __halves2half2(h0, h1);
        h[2 * i + 1] = __halves2half2(h2, h3);
        l[2 * i + 0] = __halves2half2(__float2half_rn(v.x - __half2float(h0)),
                                      __float2half_rn(v.y - __half2float(h1)));
        l[2 * i + 1] = __halves2half2(__float2half_rn(v.z - __half2float(h2)),
                                      __float2half_rn(v.w - __half2float(h3)));
    }
}

// ---------------- LayerNorm (+relu), fp32 or hi/lo output ------------------
template<bool RELU, bool HILO>
__global__ __launch_bounds__(256)
void ln_kernel(const float* __restrict__ in, float* __restrict__ outf,
               __half* __restrict__ outh, __half* __restrict__ outl,
               const float* __restrict__ gamma, const float* __restrict__ beta,
               int out_mul, int out_off)
{
    const int r = blockIdx.x, tid = threadIdx.x;
    const float4 xv = ((const float4*)(in + (size_t)r * DD))[tid];
    float s = xv.x + xv.y + xv.z + xv.w;
    float q = xv.x * xv.x + xv.y * xv.y + xv.z * xv.z + xv.w * xv.w;
    #pragma unroll
    for (int o = 16; o > 0; o >>= 1) {
        s += __shfl_xor_sync(0xffffffffu, s, o);
        q += __shfl_xor_sync(0xffffffffu, q, o);
    }
    __shared__ float sh_s[8], sh_q[8];
    const int lane = tid & 31, wid = tid >> 5;
    if (lane == 0) { sh_s[wid] = s; sh_q[wid] = q; }
    __syncthreads();
    if (wid == 0) {
        s = (lane < 8) ? sh_s[lane] : 0.f;
        q = (lane < 8) ? sh_q[lane] : 0.f;
        #pragma unroll
        for (int o = 4; o > 0; o >>= 1) {
            s += __shfl_xor_sync(0xffffffffu, s, o);
            q += __shfl_xor_sync(0xffffffffu, q, o);
        }
        if (lane == 0) { sh_s[0] = s; sh_q[0] = q; }
    }
    __syncthreads();
    const float mu  = sh_s[0] * (1.f / DD);
    const float var = sh_q[0] * (1.f / DD) - mu * mu;
    const float inv = rsqrtf(var + LN_EPS);
    const float4 g = ((const float4*)gamma)[tid];
    const float4 b = ((const float4*)beta)[tid];
    float y0 = (xv.x - mu) * inv * g.x + b.x;
    float y1 = (xv.y - mu) * inv * g.y + b.y;
    float y2 = (xv.z - mu) * inv * g.z + b.z;
    float y3 = (xv.w - mu) * inv * g.w + b.w;
    if (RELU) {
        y0 = fmaxf(y0, 0.f); y1 = fmaxf(y1, 0.f);
        y2 = fmaxf(y2, 0.f); y3 = fmaxf(y3, 0.f);
    }
    const size_t orow = (size_t)(r * out_mul + out_off) * DD;
    if (!HILO) {
        ((float4*)(outf + orow))[tid] = make_float4(y0, y1, y2, y3);
    } else {
        const __half h0 = __float2half_rn(y0), h1 = __float2half_rn(y1);
        const __half h2 = __float2half_rn(y2), h3 = __float2half_rn(y3);
        __half2* hp = (__half2*)(outh + orow + tid * 4);
        hp[0] = __halves2half2(h0, h1); hp[1] = __halves2half2(h2, h3);
        __half2* lp = (__half2*)(outl + orow + tid * 4);
        lp[0] = __halves2half2(__float2half_rn(y0 - __half2float(h0)),
                               __float2half_rn(y1 - __half2float(h1)));
        lp[1] = __halves2half2(__float2half_rn(y2 - __half2float(h2)),
                               __float2half_rn(y3 - __half2float(h3)));
    }
}

// ---------------- GAT 2-row attention fixup --------------------------------
template<int H, bool RELU, bool HILO>
__global__ __launch_bounds__(256)
void gat_fixup(const float* __restrict__ raw, const float* __restrict__ a_src,
               const float* __restrict__ a_dst, const float* __restrict__ bias,
               float* __restrict__ outf,
               __half* __restrict__ outh, __half* __restrict__ outl)
{
    constexpr int C = DD, RL = H * C;
    const int tid = threadIdx.x;
    float p[4 * H];
    #pragma unroll
    for (int q = 0; q < 4 * H; q++) p[q] = 0.f;
    for (int c = tid; c < C; c += 256) {
        #pragma unroll
        for (int h = 0; h < H; h++) {
            const float x0 = raw[h * C + c];
            const float x1 = raw[RL + h * C + c];
            const float vs = a_src[h * C + c];
            const float vd = a_dst[h * C + c];
            p[h * 4 + 0] += x0 * vs; p[h * 4 + 1] += x0 * vd;
            p[h * 4 + 2] += x1 * vs; p[h * 4 + 3] += x1 * vd;
        }
    }
    __shared__ float red[4 * H][256];
    #pragma unroll
    for (int q = 0; q < 4 * H; q++) red[q][tid] = p[q];
    __syncthreads();
    for (int s = 128; s > 0; s >>= 1) {
        if (tid < s) {
            #pragma unroll
            for (int q = 0; q < 4 * H; q++) red[q][tid] += red[q][tid + s];
        }
        __syncthreads();
    }
    __shared__ float wts[H][4];
    if (tid == 0) {
        for (int h = 0; h < H; h++) {
            const float s0 = red[h * 4 + 0][0], d0 = red[h * 4 + 1][0];
            const float s1 = red[h * 4 + 2][0], d1 = red[h * 4 + 3][0];
            const float e00 = (s0 + d0 > 0.f) ? (s0 + d0) : SLOPE * (s0 + d0);
            const float e10 = (s1 + d0 > 0.f) ? (s1 + d0) : SLOPE * (s1 + d0);
            const float m0 = fmaxf(e00, e10);
            const float a0 = expf(e00 - m0), c0 = expf(e10 - m0);
            const float r0 = 1.f / (a0 + c0);
            wts[h][0] = a0 * r0; wts[h][1] = c0 * r0;
            const float e11 = (s1 + d1 > 0.f) ? (s1 + d1) : SLOPE * (s1 + d1);
            const float e01 = (s0 + d1 > 0.f) ? (s0 + d1) : SLOPE * (s0 + d1);
            const float m1 = fmaxf(e11, e01);
            const float a1 = expf(e11 - m1), c1 = expf(e01 - m1);
            const float r1 = 1.f / (a1 + c1);
            wts[h][2] = a1 * r1; wts[h][3] = c1 * r1;
        }
    }
    __syncthreads();
    for (int idx = tid; idx < RL; idx += 256) {
        const int h = idx / C;
        const float x0 = raw[idx], x1 = raw[RL + idx];
        const float bb = bias[idx];
        float o0 = wts[h][0] * x0 + wts[h][1] * x1 + bb;
        float o1 = wts[h][2] * x1 + wts[h][3] * x0 + bb;
        if (RELU) { o0 = fmaxf(o0, 0.f); o1 = fmaxf(o1, 0.f); }
        if (!HILO) {
            outf[idx] = o0; outf[RL + idx] = o1;
        } else {
            const __half h0 = __float2half_rn(o0), h1 = __float2half_rn(o1);
            outh[idx] = h0; outh[RL + idx] = h1;
            outl[idx]      = __float2half_rn(o0 - __half2float(h0));
            outl[RL + idx] = __float2half_rn(o1 - __half2float(h1));
        }
    }
}

// ---------------- pair mean -> hi/lo ---------------------------------------
__global__ __launch_bounds__(256)
void mean_pairs(const float* __restrict__ g2, __half* __restrict__ fh,
                __half* __restrict__ fl)
{
    const int f = blockIdx.x * blockDim.x + threadIdx.x;
    constexpr int RL4 = DD / 4;
    if (f < BB * RL4) {
        const int b = f / RL4, r = f - b * RL4;
        const float4 u = ((const float4*)g2)[(size_t)(2 * b) * RL4 + r];
        const float4 v = ((const float4*)g2)[(size_t)(2 * b + 1) * RL4 + r];
        const float y0 = 0.5f * (u.x + v.x), y1 = 0.5f * (u.y + v.y);
        const float y2 = 0.5f * (u.z + v.z), y3 = 0.5f * (u.w + v.w);
        const __half h0 = __float2half_rn(y0), h1 = __float2half_rn(y1);
        const __half h2 = __float2half_rn(y2), h3 = __float2half_rn(y3);
        __half2* hp = (__half2*)(fh + (size_t)f * 4);
        hp[0] = __halves2half2(h0, h1); hp[1] = __halves2half2(h2, h3);
        __half2* lp = (__half2*)(fl + (size_t)f * 4);
        lp[0] = __halves2half2(__float2half_rn(y0 - __half2float(h0)),
                               __float2half_rn(y1 - __half2float(h1)));
        lp[1] = __halves2half2(__float2half_rn(y2 - __half2float(h2)),
                               __float2half_rn(y3 - __half2float(h3)));
    }
}

// ---------------------------------------------------------------------------
extern "C" void kernel_launch(void* const* d_in, const int* in_sizes, int n_in,
                              void* d_out, int out_size)
{
    const float* audio = (const float*)d_in[0];
    const float* text  = (const float*)d_in[1];
    const float* Wa    = (const float*)d_in[2];
    const float* ba    = (const float*)d_in[3];
    const float* lna_g = (const float*)d_in[4];
    const float* lna_b = (const float*)d_in[5];
    const float* Wt    = (const float*)d_in[6];
    const float* bt    = (const float*)d_in[7];
    const float* lnt_g = (const float*)d_in[8];
    const float* lnt_b = (const float*)d_in[9];
    const float* W1    = (const float*)d_in[10];
    const float* as1   = (const float*)d_in[11];
    const float* ad1   = (const float*)d_in[12];
    const float* b1    = (const float*)d_in[13];
    const float* W2    = (const float*)d_in[14];
    const float* as2   = (const float*)d_in[15];
    const float* ad2   = (const float*)d_in[16];
    const float* b2    = (const float*)d_in[17];
    const float* Wf    = (const float*)d_in[18];
    const float* bf    = (const float*)d_in[19];
    const float* lnf_g = (const float*)d_in[20];
    const float* lnf_b = (const float*)d_in[21];
    float* out = (float*)d_out;

    __half *ah, *al, *th, *tl, *Wah, *Wal, *Wth, *Wtl, *W1h, *W1l, *W2h, *W2l, *Wfh, *Wfl;
    __half *nh, *nl, *g1h, *g1l, *fh, *fl;
    float *proj0, *proj1, *g2, *raw1, *raw2;
    cudaGetSymbolAddress((void**)&ah,  g_ah);  cudaGetSymbolAddress((void**)&al,  g_al);
    cudaGetSymbolAddress((void**)&th,  g_th);  cudaGetSymbolAddress((void**)&tl,  g_tl);
    cudaGetSymbolAddress((void**)&Wah, g_Wah); cudaGetSymbolAddress((void**)&Wal, g_Wal);
    cudaGetSymbolAddress((void**)&Wth, g_Wth); cudaGetSymbolAddress((void**)&Wtl, g_Wtl);
    cudaGetSymbolAddress((void**)&W1h, g_W1h); cudaGetSymbolAddress((void**)&W1l, g_W1l);
    cudaGetSymbolAddress((void**)&W2h, g_W2h); cudaGetSymbolAddress((void**)&W2l, g_W2l);
    cudaGetSymbolAddress((void**)&Wfh, g_Wfh); cudaGetSymbolAddress((void**)&Wfl, g_Wfl);
    cudaGetSymbolAddress((void**)&nh,  g_nh);  cudaGetSymbolAddress((void**)&nl,  g_nl);
    cudaGetSymbolAddress((void**)&g1h, g_g1h); cudaGetSymbolAddress((void**)&g1l, g_g1l);
    cudaGetSymbolAddress((void**)&fh,  g_fh);  cudaGetSymbolAddress((void**)&fl,  g_fl);
    cudaGetSymbolAddress((void**)&proj0, g_proj0); cudaGetSymbolAddress((void**)&proj1, g_proj1);
    cudaGetSymbolAddress((void**)&g2,  g_g2);
    cudaGetSymbolAddress((void**)&raw1, g_raw1); cudaGetSymbolAddress((void**)&raw2, g_raw2);

    cudaFuncSetAttribute(gemm_tc<0>, cudaFuncAttributeMaxDynamicSharedMemorySize, SMEM_GEMM);
    cudaFuncSetAttribute(gemm_tc<1>, cudaFuncAttributeMaxDynamicSharedMemorySize, SMEM_GEMM);

    const dim3 blk(256);
    auto cvt = [&](const float* src, __half* h, __half* l, int n) {
        cvt_hilo<<<(n / 4 + 255) / 256, blk>>>((const float4*)src, (__half2*)h,
                                               (__half2*)l, n / 4);
    };

    // operand conversion to fp16 hi/lo
    cvt(audio, ah, al, BB * DD);
    cvt(text,  th, tl, BB * DD);
    cvt(Wa, Wah, Wal, DD * DD);
    cvt(Wt, Wth, Wtl, DD * DD);
    cvt(W1, W1h, W1l, HD * DD);
    cvt(W2, W2h, W2l, DD * HD);
    cvt(Wf, Wfh, Wfl, DD * DD);

    // Stage A: projections + LN + relu (interleaved hi/lo node features)
    const dim3 gP(DD / BN, BB / BM);
    gemm_tc<0><<<gP, blk, SMEM_GEMM>>>(ah, al, Wah, Wal, ba, proj0, nullptr, nullptr,
                                       BB, DD, DD, nullptr);
    gemm_tc<0><<<gP, blk, SMEM_GEMM>>>(th, tl, Wth, Wtl, bt, proj1, nullptr, nullptr,
                                       BB, DD, DD, nullptr);
    ln_kernel<true, true><<<BB, blk>>>(proj0, nullptr, nh, nl, lna_g, lna_b, 2, 0);
    ln_kernel<true, true><<<BB, blk>>>(proj1, nullptr, nh, nl, lnt_g, lnt_b, 2, 1);

    // Stage B: gat1 (GEMM + bias + relu -> hi/lo) + 2-row fixup
    const dim3 g1g(HD / BN, N2 / BM);
    gemm_tc<1><<<g1g, blk, SMEM_GEMM>>>(nh, nl, W1h, W1l, b1, nullptr, g1h, g1l,
                                        N2, HD, DD, raw1);
    gat_fixup<2, true, true><<<1, blk>>>(raw1, as1, ad1, b1, nullptr, g1h, g1l);

    // Stage C: gat2 (GEMM + bias -> fp32) + fixup
    const dim3 g2g(DD / BN, N2 / BM);
    gemm_tc<0><<<g2g, blk, SMEM_GEMM>>>(g1h, g1l, W2h, W2l, b2, g2, nullptr, nullptr,
                                        N2, DD, HD, raw2);
    gat_fixup<1, false, false><<<1, blk>>>(raw2, as2, ad2, b2, g2, nullptr, nullptr);

    // Stage D: pair mean -> hi/lo, fc GEMM, final LN
    mean_pairs<<<(BB * DD / 4 + 255) / 256, blk>>>(g2, fh, fl);
    gemm_tc<0><<<gP, blk, SMEM_GEMM>>>(fh, fl, Wfh, Wfl, bf, proj0, nullptr, nullptr,
                                       BB, DD, DD, nullptr);
    ln_kernel<false, false><<<BB, blk>>>(proj0, out, nullptr, nullptr, lnf_g, lnf_b, 1, 0);
}